// round 16
// baseline (speedup 1.0000x reference)
#include <cuda_runtime.h>
#include <math.h>

#define BATCH 1024
#define TSTEPS 32
#define HID 128
#define GATESZ 512
#define FEATSZ 4608
#define ACTD 26
#define KTOT (FEATSZ + HID)   // 4736
#define MWID 1024             // mask(900) + act(26) + zero pad

// ---------------- device scratch ----------------
__device__ float g_msk[BATCH * 900];
__device__ float g_h[BATCH * HID];
__device__ float g_c[BATCH * HID];
__device__ float g_feat[BATCH * FEATSZ];
__device__ float g_gates[BATCH * GATESZ];
__device__ float g_w1t[FEATSZ * GATESZ];    // w_ih^T  [k][n], tf32
__device__ float g_w2t[HID * GATESZ];       // w_hh^T  [k][n], tf32
__device__ float g_wmt[HID * MWID];         // [msk_w | act_w | 0]^T, tf32

// fast transcendentals (MUFU-based)
__device__ __forceinline__ float sigf(float x) {
    return __fdividef(1.f, 1.f + __expf(-x));
}
__device__ __forceinline__ float tanf_fast(float x) {
    return __fdividef(2.f, 1.f + __expf(-2.f * x)) - 1.f;
}

__device__ __forceinline__ unsigned f2tf32(float x) {
    unsigned r;
    asm("cvt.rna.tf32.f32 %0, %1;" : "=r"(r) : "f"(x));
    return r;
}

// ---- packed fp32x2 helpers ----
typedef unsigned long long ull;
__device__ __forceinline__ ull pk2(float x, float y) {
    ull r; asm("mov.b64 %0, {%1,%2};" : "=l"(r) : "f"(x), "f"(y)); return r;
}
__device__ __forceinline__ float2 upk2(ull v) {
    float2 f; asm("mov.b64 {%0,%1}, %2;" : "=f"(f.x), "=f"(f.y) : "l"(v)); return f;
}
__device__ __forceinline__ ull fma2(ull a, ull b, ull c) {
    ull d; asm("fma.rn.f32x2 %0, %1, %2, %3;" : "=l"(d) : "l"(a), "l"(b), "l"(c));
    return d;
}

// ---- cp.async helpers ----
__device__ __forceinline__ void cpasync16(float* smem, const float* g) {
    unsigned s = (unsigned)__cvta_generic_to_shared(smem);
    asm volatile("cp.async.cg.shared.global [%0],[%1],16;" :: "r"(s), "l"(g));
}
__device__ __forceinline__ void cp_commit() {
    asm volatile("cp.async.commit_group;");
}
template <int N>
__device__ __forceinline__ void cp_wait() {
    asm volatile("cp.async.wait_group %0;" :: "n"(N));
}
__device__ __forceinline__ void grp_bar(int id) {
    asm volatile("bar.sync %0, 128;" :: "r"(id) : "memory");
}

// ---------------- init state ----------------
__global__ void init_state() {
    int i = blockIdx.x * blockDim.x + threadIdx.x;
    if (i < BATCH * 900) g_msk[i] = 1.f;
    if (i < BATCH * HID) { g_h[i] = 0.f; g_c[i] = 0.f; }
}

// ---------------- weight prep ----------------
// Tiled transpose: both read and write coalesced (w is [GATESZ][FEATSZ]).
__global__ void transpose_wih(const float* __restrict__ w) {
    __shared__ float tile[32][33];
    const int kb = blockIdx.x * 32, nb = blockIdx.y * 32;
    const int tx = threadIdx.x, ty = threadIdx.y;   // (32,8)
#pragma unroll
    for (int i = 0; i < 32; i += 8)
        tile[ty + i][tx] = w[(size_t)(nb + ty + i) * FEATSZ + kb + tx];
    __syncthreads();
#pragma unroll
    for (int i = 0; i < 32; i += 8)
        g_w1t[(size_t)(kb + ty + i) * GATESZ + nb + tx] =
            __uint_as_float(f2tf32(tile[tx][ty + i]));
}
__global__ void transpose_whh(const float* __restrict__ w) {
    int i = blockIdx.x * 256 + threadIdx.x;
    if (i < HID * GATESZ) {
        int k = i / GATESZ, n = i % GATESZ;
        g_w2t[i] = __uint_as_float(f2tf32(w[n * HID + k]));
    }
}
__global__ void transpose_wm(const float* __restrict__ mw, const float* __restrict__ aw) {
    int i = blockIdx.x * 256 + threadIdx.x;
    if (i < HID * MWID) {
        int k = i / MWID, n = i % MWID;
        float v = 0.f;
        if (n < 900)       v = mw[n * HID + k];
        else if (n < 926)  v = aw[(n - 900) * HID + k];
        g_wmt[i] = __uint_as_float(f2tf32(v));
    }
}

// ---------------- fused mask-mul + conv1/2/3, 2 samples/block, f32x2 ----
// 512 threads: 2 warps per output channel (row-split halves) -> 32 warps/SM.
__global__ void __launch_bounds__(512) conv_kernel(
        const float* __restrict__ batch,
        const float* __restrict__ c1w, const float* __restrict__ c1b,
        const float* __restrict__ c2w, const float* __restrict__ c2b,
        const float* __restrict__ c3w, const float* __restrict__ c3b) {
    extern __shared__ float sm[];
    float2* s_in = (float2*)sm;            // 900
    float2* s_t1 = s_in + 900;             // 6272
    float2* s_t2 = s_t1 + 6272;            // 5408
    float*  s_w2 = (float*)(s_t2 + 5408);  // 576
    float*  s_w3 = s_w2 + 576;             // 576

    const int b0 = blockIdx.x * 2, b1 = b0 + 1;
    const int tid = threadIdx.x;

    for (int i = tid; i < 900; i += 512) {
        float lo = batch[b0 * 900 + i] * g_msk[b0 * 900 + i];
        float hi = batch[b1 * 900 + i] * g_msk[b1 * 900 + i];
        s_in[i] = make_float2(lo, hi);
    }
    for (int i = tid; i < 576; i += 512) { s_w2[i] = c2w[i]; s_w3[i] = c3w[i]; }
    __syncthreads();

    const int wid = tid >> 5;
    const int oc = wid & 7;
    const int half = wid >> 3;    // 0 or 1: row-split
    const int lane = tid & 31;

    // conv1: 1x30x30 -> 8x28x28 ; half h owns rows [14h, 14h+14)
    {
        const int base = half * 14;
        ull acc[14];
        ull bias = pk2(c1b[oc], c1b[oc]);
#pragma unroll
        for (int r = 0; r < 14; r++) acc[r] = bias;
        ull w[9];
#pragma unroll
        for (int i = 0; i < 9; i++) { float v = c1w[oc * 9 + i]; w[i] = pk2(v, v); }
        if (lane < 28) {
#pragma unroll
            for (int rl = 0; rl < 16; rl++) {
                const int rr = base + rl;
                ull i0 = *(const ull*)&s_in[rr * 30 + lane];
                ull i1 = *(const ull*)&s_in[rr * 30 + lane + 1];
                ull i2 = *(const ull*)&s_in[rr * 30 + lane + 2];
#pragma unroll
                for (int dr = 0; dr < 3; dr++) {
                    const int rA = rl - dr;                 // compile-time index
                    if (rA >= 0 && rA < 14) {
                        acc[rA] = fma2(i0, w[dr * 3 + 0], acc[rA]);
                        acc[rA] = fma2(i1, w[dr * 3 + 1], acc[rA]);
                        acc[rA] = fma2(i2, w[dr * 3 + 2], acc[rA]);
                    }
                }
            }
#pragma unroll
            for (int r = 0; r < 14; r++) {
                float2 v = upk2(acc[r]);
                s_t1[oc * 784 + (base + r) * 28 + lane] =
                    make_float2(fmaxf(v.x, 0.f), fmaxf(v.y, 0.f));
            }
        }
    }
    __syncthreads();

    // conv2: 8x28x28 -> 8x26x26 ; half h owns rows [13h, 13h+13)
    {
        const int base = half * 13;
        ull acc[13];
        ull bias = pk2(c2b[oc], c2b[oc]);
#pragma unroll
        for (int r = 0; r < 13; r++) acc[r] = bias;
        if (lane < 26) {
            for (int ic = 0; ic < 8; ic++) {
                ull w[9];
#pragma unroll
                for (int i = 0; i < 9; i++) {
                    float v = s_w2[(oc * 8 + ic) * 9 + i];
                    w[i] = pk2(v, v);
                }
                const float2* inb = s_t1 + ic * 784;
#pragma unroll
                for (int rl = 0; rl < 15; rl++) {
                    const int rr = base + rl;
                    ull i0 = *(const ull*)&inb[rr * 28 + lane];
                    ull i1 = *(const ull*)&inb[rr * 28 + lane + 1];
                    ull i2 = *(const ull*)&inb[rr * 28 + lane + 2];
#pragma unroll
                    for (int dr = 0; dr < 3; dr++) {
                        const int rA = rl - dr;
                        if (rA >= 0 && rA < 13) {
                            acc[rA] = fma2(i0, w[dr * 3 + 0], acc[rA]);
                            acc[rA] = fma2(i1, w[dr * 3 + 1], acc[rA]);
                            acc[rA] = fma2(i2, w[dr * 3 + 2], acc[rA]);
                        }
                    }
                }
            }
#pragma unroll
            for (int r = 0; r < 13; r++) {
                float2 v = upk2(acc[r]);
                s_t2[oc * 676 + (base + r) * 26 + lane] =
                    make_float2(fmaxf(v.x, 0.f), fmaxf(v.y, 0.f));
            }
        }
    }
    __syncthreads();

    // conv3: 8x26x26 -> 8x24x24 ; half h owns rows [12h, 12h+12) (+RNA store)
    {
        const int base = half * 12;
        ull acc[12];
        ull bias = pk2(c3b[oc], c3b[oc]);
#pragma unroll
        for (int r = 0; r < 12; r++) acc[r] = bias;
        if (lane < 24) {
            for (int ic = 0; ic < 8; ic++) {
                ull w[9];
#pragma unroll
                for (int i = 0; i < 9; i++) {
                    float v = s_w3[(oc * 8 + ic) * 9 + i];
                    w[i] = pk2(v, v);
                }
                const float2* inb = s_t2 + ic * 676;
#pragma unroll
                for (int rl = 0; rl < 14; rl++) {
                    const int rr = base + rl;
                    ull i0 = *(const ull*)&inb[rr * 26 + lane];
                    ull i1 = *(const ull*)&inb[rr * 26 + lane + 1];
                    ull i2 = *(const ull*)&inb[rr * 26 + lane + 2];
#pragma unroll
                    for (int dr = 0; dr < 3; dr++) {
                        const int rA = rl - dr;
                        if (rA >= 0 && rA < 12) {
                            acc[rA] = fma2(i0, w[dr * 3 + 0], acc[rA]);
                            acc[rA] = fma2(i1, w[dr * 3 + 1], acc[rA]);
                            acc[rA] = fma2(i2, w[dr * 3 + 2], acc[rA]);
                        }
                    }
                }
            }
#pragma unroll
            for (int r = 0; r < 12; r++) {
                float2 v = upk2(acc[r]);
                g_feat[(size_t)b0 * FEATSZ + oc * 576 + (base + r) * 24 + lane] =
                    __uint_as_float(f2tf32(fmaxf(v.x, 0.f)));
                g_feat[(size_t)b1 * FEATSZ + oc * 576 + (base + r) * 24 + lane] =
                    __uint_as_float(f2tf32(fmaxf(v.y, 0.f)));
            }
        }
    }
}

// ---------------- TF32 MMA ----------------
__device__ __forceinline__ void mma_tf32(float* c, const unsigned* a, const unsigned* b) {
    asm volatile(
        "mma.sync.aligned.m16n8k8.row.col.f32.tf32.tf32.f32 "
        "{%0,%1,%2,%3}, {%4,%5,%6,%7}, {%8,%9}, {%0,%1,%2,%3};"
        : "+f"(c[0]), "+f"(c[1]), "+f"(c[2]), "+f"(c[3])
        : "r"(a[0]), "r"(a[1]), "r"(a[2]), "r"(a[3]), "r"(b[0]), "r"(b[1]));
}

// ---------------- gates GEMM: 2 warp-groups, K-split, 3-stage cp.async (R13) ----
#define GCH 64
#define NCH (KTOT / GCH)    // 74
#define FCH (FEATSZ / GCH)  // 72
#define HCH (NCH / 2)       // 37
#define AS_STRIDE 68
#define BS_STRIDE 72
#define AS_SZ (64 * AS_STRIDE)
#define BS_SZ (64 * BS_STRIDE)
#define GATES_SMEM ((6 * AS_SZ + 6 * BS_SZ) * sizeof(float))   // 215040 B
#define RS_STRIDE 66

__global__ void __launch_bounds__(256) gates_gemm_tc() {
    extern __shared__ float smem[];
    float* Abase = smem;
    float* Bbase = smem + 6 * AS_SZ;

    const int tid = threadIdx.x;
    const int gtid = tid & 127;
    const int group = tid >> 7;
    const int m0 = blockIdx.y * 64, n0 = blockIdx.x * 64;
    const int wid4 = (tid >> 5) & 3, lane = tid & 31;
    const int wm = (wid4 >> 1) * 32, wn = (wid4 & 1) * 32;
    const int grp = lane >> 2, tg = lane & 3;

    float acc[2][4][4];
#pragma unroll
    for (int i = 0; i < 2; i++)
#pragma unroll
        for (int j = 0; j < 4; j++)
#pragma unroll
            for (int e = 0; e < 4; e++) acc[i][j][e] = 0.f;

    auto issue = [&](int c, int st) {
        float* a = Abase + (group * 3 + st) * AS_SZ;
        float* b = Bbase + (group * 3 + st) * BS_SZ;
#pragma unroll
        for (int i = 0; i < 8; i++) {
            int s = i * 128 + gtid;
            int row = s >> 4, cs = (s & 15) * 4;
            const float* ga = (c < FCH)
                ? g_feat + (size_t)(m0 + row) * FEATSZ + c * GCH + cs
                : g_h    + (size_t)(m0 + row) * HID + (c - FCH) * GCH + cs;
            cpasync16(a + row * AS_STRIDE + cs, ga);
            const float* gb = (c < FCH)
                ? g_w1t + (size_t)(c * GCH + row) * GATESZ + n0 + cs
                : g_w2t + (size_t)((c - FCH) * GCH + row) * GATESZ + n0 + cs;
            cpasync16(b + row * BS_STRIDE + cs, gb);
        }
    };

    const int c0 = group * HCH;
    issue(c0, 0);
    cp_commit();
    issue(c0 + 1, 1);
    cp_commit();

    for (int ci = 0; ci < HCH; ci++) {
        if (ci + 2 < HCH) {
            issue(c0 + ci + 2, (ci + 2) % 3);
            cp_commit();
            cp_wait<2>();
        } else if (ci + 1 < HCH) {
            cp_wait<1>();
        } else {
            cp_wait<0>();
        }
        grp_bar(group + 1);

        const int st = ci % 3;
        const float* a_s = Abase + (group * 3 + st) * AS_SZ;
        const float* b_s = Bbase + (group * 3 + st) * BS_SZ;
#pragma unroll
        for (int kk = 0; kk < 8; kk++) {
            const int kb = kk * 8;
            unsigned a[2][4], b[4][2];
#pragma unroll
            for (int i = 0; i < 2; i++) {
                int r = wm + i * 16 + grp;
                a[i][0] = __float_as_uint(a_s[r * AS_STRIDE + kb + tg]);
                a[i][1] = __float_as_uint(a_s[(r + 8) * AS_STRIDE + kb + tg]);
                a[i][2] = __float_as_uint(a_s[r * AS_STRIDE + kb + tg + 4]);
                a[i][3] = __float_as_uint(a_s[(r + 8) * AS_STRIDE + kb + tg + 4]);
            }
#pragma unroll
            for (int j = 0; j < 4; j++) {
                int cn = wn + j * 8 + grp;
                b[j][0] = __float_as_uint(b_s[(kb + tg) * BS_STRIDE + cn]);
                b[j][1] = __float_as_uint(b_s[(kb + tg + 4) * BS_STRIDE + cn]);
            }
#pragma unroll
            for (int i = 0; i < 2; i++)
#pragma unroll
                for (int j = 0; j < 4; j++)
                    mma_tf32(acc[i][j], a[i], b[j]);
        }
        grp_bar(group + 1);
    }

    // cross-group reduction
    float* Rs = smem;
    __syncthreads();
    if (group == 1) {
#pragma unroll
        for (int i = 0; i < 2; i++)
#pragma unroll
            for (int j = 0; j < 4; j++) {
                int lr = wm + i * 16 + grp;
                int lc = wn + j * 8 + tg * 2;
                *(float2*)&Rs[lr * RS_STRIDE + lc] = make_float2(acc[i][j][0], acc[i][j][1]);
                *(float2*)&Rs[(lr + 8) * RS_STRIDE + lc] = make_float2(acc[i][j][2], acc[i][j][3]);
            }
    }
    __syncthreads();
    if (group == 0) {
#pragma unroll
        for (int i = 0; i < 2; i++)
#pragma unroll
            for (int j = 0; j < 4; j++) {
                int lr = wm + i * 16 + grp;
                int lc = wn + j * 8 + tg * 2;
                float2 p0 = *(const float2*)&Rs[lr * RS_STRIDE + lc];
                float2 p1 = *(const float2*)&Rs[(lr + 8) * RS_STRIDE + lc];
                int row = m0 + lr;
                int col = n0 + lc;
                *(float2*)&g_gates[(size_t)row * GATESZ + col] =
                    make_float2(acc[i][j][0] + p0.x, acc[i][j][1] + p0.y);
                *(float2*)&g_gates[(size_t)(row + 8) * GATESZ + col] =
                    make_float2(acc[i][j][2] + p1.x, acc[i][j][3] + p1.y);
            }
    }
}

// ---------------- LSTM pointwise (fast transcendentals, RNA rounding on h) ----------------
__global__ void lstm_pw(const float* __restrict__ b_ih, const float* __restrict__ b_hh) {
    int idx = blockIdx.x * blockDim.x + threadIdx.x;
    int b = idx >> 7, j = idx & 127;
    const float* g = g_gates + (size_t)b * GATESZ;
    float gi = g[j]        + b_ih[j]        + b_hh[j];
    float gf = g[128 + j]  + b_ih[128 + j]  + b_hh[128 + j];
    float gg = g[256 + j]  + b_ih[256 + j]  + b_hh[256 + j];
    float go = g[384 + j]  + b_ih[384 + j]  + b_hh[384 + j];
    float cn = sigf(gf) * g_c[idx] + sigf(gi) * tanf_fast(gg);
    g_c[idx] = cn;
    g_h[idx] = __uint_as_float(f2tf32(sigf(go) * tanf_fast(cn)));
}

// ---------------- mask+act head GEMM: 2 n-tiles per block, shared A (R13) ----------------
#define MAS_STRIDE 132
#define MAS_SZ (64 * MAS_STRIDE)
#define MBS_SZ (128 * BS_STRIDE)
#define MASK_SMEM ((MAS_SZ + 2 * MBS_SZ) * sizeof(float))

__global__ void __launch_bounds__(256) maskact_gemm(const float* __restrict__ msk_b,
                                                    const float* __restrict__ act_b,
                                                    float* __restrict__ out_msks,
                                                    float* __restrict__ out_acts, int t) {
    extern __shared__ float smem[];
    float* As = smem;
    const int tid = threadIdx.x;
    const int gtid = tid & 127;
    const int group = tid >> 7;
    float* Bs = smem + MAS_SZ + group * MBS_SZ;

    const int n0 = blockIdx.x * 128 + group * 64;
    const int m0 = blockIdx.y * 64;
    const int wid4 = (tid >> 5) & 3, lane = tid & 31;
    const int wm = (wid4 >> 1) * 32, wn = (wid4 & 1) * 32;
    const int grp = lane >> 2, tg = lane & 3;

#pragma unroll
    for (int i = 0; i < 8; i++) {
        int s = i * 256 + tid;
        int row = s >> 5, cs = (s & 31) * 4;
        cpasync16(As + row * MAS_STRIDE + cs, g_h + (size_t)(m0 + row) * HID + cs);
    }
#pragma unroll
    for (int i = 0; i < 16; i++) {
        int s = i * 128 + gtid;
        int row = s >> 4, cs = (s & 15) * 4;
        cpasync16(Bs + row * BS_STRIDE + cs, g_wmt + (size_t)row * MWID + n0 + cs);
    }
    cp_commit();
    cp_wait<0>();
    __syncthreads();

    float acc[2][4][4];
#pragma unroll
    for (int i = 0; i < 2; i++)
#pragma unroll
        for (int j = 0; j < 4; j++)
#pragma unroll
            for (int e = 0; e < 4; e++) acc[i][j][e] = 0.f;

#pragma unroll
    for (int kk = 0; kk < 16; kk++) {
        const int kb = kk * 8;
        unsigned a[2][4], b[4][2];
#pragma unroll
        for (int i = 0; i < 2; i++) {
            int r = wm + i * 16 + grp;
            a[i][0] = __float_as_uint(As[r * MAS_STRIDE + kb + tg]);
            a[i][1] = __float_as_uint(As[(r + 8) * MAS_STRIDE + kb + tg]);
            a[i][2] = __float_as_uint(As[r * MAS_STRIDE + kb + tg + 4]);
            a[i][3] = __float_as_uint(As[(r + 8) * MAS_STRIDE + kb + tg + 4]);
        }
#pragma unroll
        for (int j = 0; j < 4; j++) {
            int cn = wn + j * 8 + grp;
            b[j][0] = __float_as_uint(Bs[(kb + tg) * BS_STRIDE + cn]);
            b[j][1] = __float_as_uint(Bs[(kb + tg + 4) * BS_STRIDE + cn]);
        }
#pragma unroll
        for (int i = 0; i < 2; i++)
#pragma unroll
            for (int j = 0; j < 4; j++)
                mma_tf32(acc[i][j], a[i], b[j]);
    }

#pragma unroll
    for (int i = 0; i < 2; i++) {
#pragma unroll
        for (int j = 0; j < 4; j++) {
            int row = m0 + wm + i * 16 + grp;
            int col = n0 + wn + j * 8 + tg * 2;
#pragma unroll
            for (int e = 0; e < 4; e++) {
                int m = row + (e >> 1) * 8;
                int n = col + (e & 1);
                float x = acc[i][j][e];
                if (n < 900) {
                    float v = sigf(x + msk_b[n]);
                    g_msk[(size_t)m * 900 + n] = v;
                    out_msks[((size_t)m * TSTEPS + t) * 900 + n] = v;
                } else if (n < 926) {
                    out_acts[((size_t)m * TSTEPS + t) * ACTD + (n - 900)] = x + act_b[n - 900];
                }
            }
        }
    }
}

// ---------------- launch ----------------
extern "C" void kernel_launch(void* const* d_in, const int* in_sizes, int n_in,
                              void* d_out, int out_size) {
    const float* batch = (const float*)d_in[0];
    const float* c1w   = (const float*)d_in[1];
    const float* c1b   = (const float*)d_in[2];
    const float* c2w   = (const float*)d_in[3];
    const float* c2b   = (const float*)d_in[4];
    const float* c3w   = (const float*)d_in[5];
    const float* c3b   = (const float*)d_in[6];
    const float* w_ih  = (const float*)d_in[7];
    const float* w_hh  = (const float*)d_in[8];
    const float* b_ih  = (const float*)d_in[9];
    const float* b_hh  = (const float*)d_in[10];
    const float* msk_w = (const float*)d_in[11];
    const float* msk_b = (const float*)d_in[12];
    const float* act_w = (const float*)d_in[13];
    const float* act_b = (const float*)d_in[14];

    float* out_acts = (float*)d_out;
    float* out_msks = out_acts + (size_t)BATCH * TSTEPS * ACTD;

    const size_t conv_smem = (900 + 6272 + 5408) * sizeof(float2) + 2 * 576 * sizeof(float);
    cudaFuncSetAttribute(conv_kernel, cudaFuncAttributeMaxDynamicSharedMemorySize,
                         (int)conv_smem);
    cudaFuncSetAttribute(gates_gemm_tc, cudaFuncAttributeMaxDynamicSharedMemorySize,
                         (int)GATES_SMEM);
    cudaFuncSetAttribute(maskact_gemm, cudaFuncAttributeMaxDynamicSharedMemorySize,
                         (int)MASK_SMEM);

    init_state<<<(BATCH * 900 + 255) / 256, 256>>>();
    transpose_wih<<<dim3(FEATSZ / 32, GATESZ / 32), dim3(32, 8)>>>(w_ih);
    transpose_whh<<<(HID * GATESZ + 255) / 256, 256>>>(w_hh);
    transpose_wm<<<(HID * MWID + 255) / 256, 256>>>(msk_w, act_w);

    for (int t = 0; t < TSTEPS; t++) {
        conv_kernel<<<BATCH / 2, 512, conv_smem>>>(batch, c1w, c1b, c2w, c2b, c3w, c3b);
        gates_gemm_tc<<<dim3(GATESZ / 64, BATCH / 64), 256, GATES_SMEM>>>();
        lstm_pw<<<BATCH * HID / 256, 256>>>(b_ih, b_hh);
        maskact_gemm<<<dim3(MWID / 128, BATCH / 64), 256, MASK_SMEM>>>(msk_b, act_b,
                                                                       out_msks, out_acts, t);
    }
}

// round 17
// speedup vs baseline: 1.0395x; 1.0395x over previous
#include <cuda_runtime.h>
#include <math.h>

#define BATCH 1024
#define TSTEPS 32
#define HID 128
#define GATESZ 512
#define FEATSZ 4608
#define ACTD 26
#define KTOT (FEATSZ + HID)   // 4736
#define MWID 1024             // mask(900) + act(26) + zero pad

// ---------------- device scratch ----------------
__device__ float g_msk[BATCH * 900];
__device__ float g_h[BATCH * HID];
__device__ float g_c[BATCH * HID];
__device__ float g_feat[BATCH * FEATSZ];
__device__ float g_gates[BATCH * GATESZ];
__device__ float g_w1t[FEATSZ * GATESZ];    // w_ih^T  [k][n], tf32
__device__ float g_w2t[HID * GATESZ];       // w_hh^T  [k][n], tf32
__device__ float g_wmt[HID * MWID];         // [msk_w | act_w | 0]^T, tf32

// fast transcendentals (MUFU-based)
__device__ __forceinline__ float sigf(float x) {
    return __fdividef(1.f, 1.f + __expf(-x));
}
__device__ __forceinline__ float tanf_fast(float x) {
    return __fdividef(2.f, 1.f + __expf(-2.f * x)) - 1.f;
}

__device__ __forceinline__ unsigned f2tf32(float x) {
    unsigned r;
    asm("cvt.rna.tf32.f32 %0, %1;" : "=r"(r) : "f"(x));
    return r;
}

// ---- packed fp32x2 helpers ----
typedef unsigned long long ull;
__device__ __forceinline__ ull pk2(float x, float y) {
    ull r; asm("mov.b64 %0, {%1,%2};" : "=l"(r) : "f"(x), "f"(y)); return r;
}
__device__ __forceinline__ float2 upk2(ull v) {
    float2 f; asm("mov.b64 {%0,%1}, %2;" : "=f"(f.x), "=f"(f.y) : "l"(v)); return f;
}
__device__ __forceinline__ ull fma2(ull a, ull b, ull c) {
    ull d; asm("fma.rn.f32x2 %0, %1, %2, %3;" : "=l"(d) : "l"(a), "l"(b), "l"(c));
    return d;
}

// ---- cp.async helpers ----
__device__ __forceinline__ void cpasync16(float* smem, const float* g) {
    unsigned s = (unsigned)__cvta_generic_to_shared(smem);
    asm volatile("cp.async.cg.shared.global [%0],[%1],16;" :: "r"(s), "l"(g));
}
__device__ __forceinline__ void cp_commit() {
    asm volatile("cp.async.commit_group;");
}
template <int N>
__device__ __forceinline__ void cp_wait() {
    asm volatile("cp.async.wait_group %0;" :: "n"(N));
}
__device__ __forceinline__ void grp_bar(int id) {
    asm volatile("bar.sync %0, 128;" :: "r"(id) : "memory");
}

// ---------------- init state ----------------
__global__ void init_state() {
    int i = blockIdx.x * blockDim.x + threadIdx.x;
    if (i < BATCH * 900) g_msk[i] = 1.f;
    if (i < BATCH * HID) { g_h[i] = 0.f; g_c[i] = 0.f; }
}

// ---------------- weight prep ----------------
// Tiled transpose: both read and write coalesced (w is [GATESZ][FEATSZ]).
__global__ void transpose_wih(const float* __restrict__ w) {
    __shared__ float tile[32][33];
    const int kb = blockIdx.x * 32, nb = blockIdx.y * 32;
    const int tx = threadIdx.x, ty = threadIdx.y;   // (32,8)
#pragma unroll
    for (int i = 0; i < 32; i += 8)
        tile[ty + i][tx] = w[(size_t)(nb + ty + i) * FEATSZ + kb + tx];
    __syncthreads();
#pragma unroll
    for (int i = 0; i < 32; i += 8)
        g_w1t[(size_t)(kb + ty + i) * GATESZ + nb + tx] =
            __uint_as_float(f2tf32(tile[tx][ty + i]));
}
__global__ void transpose_whh(const float* __restrict__ w) {
    int i = blockIdx.x * 256 + threadIdx.x;
    if (i < HID * GATESZ) {
        int k = i / GATESZ, n = i % GATESZ;
        g_w2t[i] = __uint_as_float(f2tf32(w[n * HID + k]));
    }
}
__global__ void transpose_wm(const float* __restrict__ mw, const float* __restrict__ aw) {
    int i = blockIdx.x * 256 + threadIdx.x;
    if (i < HID * MWID) {
        int k = i / MWID, n = i % MWID;
        float v = 0.f;
        if (n < 900)       v = mw[n * HID + k];
        else if (n < 926)  v = aw[(n - 900) * HID + k];
        g_wmt[i] = __uint_as_float(f2tf32(v));
    }
}

// ---------------- fused mask-mul + conv1/2/3 (+ReLU), 2 samples/block, f32x2 ----
// (R13/R9 form — the validated conv optimum)
__global__ void conv_kernel(const float* __restrict__ batch,
                            const float* __restrict__ c1w, const float* __restrict__ c1b,
                            const float* __restrict__ c2w, const float* __restrict__ c2b,
                            const float* __restrict__ c3w, const float* __restrict__ c3b) {
    extern __shared__ float sm[];
    float2* s_in = (float2*)sm;            // 900
    float2* s_t1 = s_in + 900;             // 6272
    float2* s_t2 = s_t1 + 6272;            // 5408
    float*  s_w2 = (float*)(s_t2 + 5408);  // 576
    float*  s_w3 = s_w2 + 576;             // 576

    const int b0 = blockIdx.x * 2, b1 = b0 + 1;
    const int tid = threadIdx.x;

    for (int i = tid; i < 900; i += 256) {
        float lo = batch[b0 * 900 + i] * g_msk[b0 * 900 + i];
        float hi = batch[b1 * 900 + i] * g_msk[b1 * 900 + i];
        s_in[i] = make_float2(lo, hi);
    }
    for (int i = tid; i < 576; i += 256) { s_w2[i] = c2w[i]; s_w3[i] = c3w[i]; }
    __syncthreads();

    const int oc = tid >> 5;
    const int lane = tid & 31;

    // conv1
    {
        ull acc[28];
        ull bias = pk2(c1b[oc], c1b[oc]);
#pragma unroll
        for (int r = 0; r < 28; r++) acc[r] = bias;
        ull w[9];
#pragma unroll
        for (int i = 0; i < 9; i++) { float v = c1w[oc * 9 + i]; w[i] = pk2(v, v); }
        if (lane < 28) {
#pragma unroll
            for (int rr = 0; rr < 30; rr++) {
                ull i0 = *(const ull*)&s_in[rr * 30 + lane];
                ull i1 = *(const ull*)&s_in[rr * 30 + lane + 1];
                ull i2 = *(const ull*)&s_in[rr * 30 + lane + 2];
#pragma unroll
                for (int dr = 0; dr < 3; dr++) {
                    int r = rr - dr;
                    if (r >= 0 && r < 28) {
                        acc[r] = fma2(i0, w[dr * 3 + 0], acc[r]);
                        acc[r] = fma2(i1, w[dr * 3 + 1], acc[r]);
                        acc[r] = fma2(i2, w[dr * 3 + 2], acc[r]);
                    }
                }
            }
#pragma unroll
            for (int r = 0; r < 28; r++) {
                float2 v = upk2(acc[r]);
                s_t1[oc * 784 + r * 28 + lane] =
                    make_float2(fmaxf(v.x, 0.f), fmaxf(v.y, 0.f));
            }
        }
    }
    __syncthreads();

    // conv2
    {
        ull acc[26];
        ull bias = pk2(c2b[oc], c2b[oc]);
#pragma unroll
        for (int r = 0; r < 26; r++) acc[r] = bias;
        if (lane < 26) {
            for (int ic = 0; ic < 8; ic++) {
                ull w[9];
#pragma unroll
                for (int i = 0; i < 9; i++) {
                    float v = s_w2[(oc * 8 + ic) * 9 + i];
                    w[i] = pk2(v, v);
                }
                const float2* inb = s_t1 + ic * 784;
#pragma unroll
                for (int rr = 0; rr < 28; rr++) {
                    ull i0 = *(const ull*)&inb[rr * 28 + lane];
                    ull i1 = *(const ull*)&inb[rr * 28 + lane + 1];
                    ull i2 = *(const ull*)&inb[rr * 28 + lane + 2];
#pragma unroll
                    for (int dr = 0; dr < 3; dr++) {
                        int r = rr - dr;
                        if (r >= 0 && r < 26) {
                            acc[r] = fma2(i0, w[dr * 3 + 0], acc[r]);
                            acc[r] = fma2(i1, w[dr * 3 + 1], acc[r]);
                            acc[r] = fma2(i2, w[dr * 3 + 2], acc[r]);
                        }
                    }
                }
            }
#pragma unroll
            for (int r = 0; r < 26; r++) {
                float2 v = upk2(acc[r]);
                s_t2[oc * 676 + r * 26 + lane] =
                    make_float2(fmaxf(v.x, 0.f), fmaxf(v.y, 0.f));
            }
        }
    }
    __syncthreads();

    // conv3 (+RNA tf32 rounding on store)
    {
        ull acc[24];
        ull bias = pk2(c3b[oc], c3b[oc]);
#pragma unroll
        for (int r = 0; r < 24; r++) acc[r] = bias;
        if (lane < 24) {
            for (int ic = 0; ic < 8; ic++) {
                ull w[9];
#pragma unroll
                for (int i = 0; i < 9; i++) {
                    float v = s_w3[(oc * 8 + ic) * 9 + i];
                    w[i] = pk2(v, v);
                }
                const float2* inb = s_t2 + ic * 676;
#pragma unroll
                for (int rr = 0; rr < 26; rr++) {
                    ull i0 = *(const ull*)&inb[rr * 26 + lane];
                    ull i1 = *(const ull*)&inb[rr * 26 + lane + 1];
                    ull i2 = *(const ull*)&inb[rr * 26 + lane + 2];
#pragma unroll
                    for (int dr = 0; dr < 3; dr++) {
                        int r = rr - dr;
                        if (r >= 0 && r < 24) {
                            acc[r] = fma2(i0, w[dr * 3 + 0], acc[r]);
                            acc[r] = fma2(i1, w[dr * 3 + 1], acc[r]);
                            acc[r] = fma2(i2, w[dr * 3 + 2], acc[r]);
                        }
                    }
                }
            }
#pragma unroll
            for (int r = 0; r < 24; r++) {
                float2 v = upk2(acc[r]);
                g_feat[(size_t)b0 * FEATSZ + oc * 576 + r * 24 + lane] =
                    __uint_as_float(f2tf32(fmaxf(v.x, 0.f)));
                g_feat[(size_t)b1 * FEATSZ + oc * 576 + r * 24 + lane] =
                    __uint_as_float(f2tf32(fmaxf(v.y, 0.f)));
            }
        }
    }
}

// ---------------- TF32 MMA ----------------
__device__ __forceinline__ void mma_tf32(float* c, const unsigned* a, const unsigned* b) {
    asm volatile(
        "mma.sync.aligned.m16n8k8.row.col.f32.tf32.tf32.f32 "
        "{%0,%1,%2,%3}, {%4,%5,%6,%7}, {%8,%9}, {%0,%1,%2,%3};"
        : "+f"(c[0]), "+f"(c[1]), "+f"(c[2]), "+f"(c[3])
        : "r"(a[0]), "r"(a[1]), "r"(a[2]), "r"(a[3]), "r"(b[0]), "r"(b[1]));
}

// ---------------- gates GEMM: 2 warp-groups, K-split, 3-stage cp.async (R13) ----
#define GCH 64
#define NCH (KTOT / GCH)    // 74
#define FCH (FEATSZ / GCH)  // 72
#define HCH (NCH / 2)       // 37
#define AS_STRIDE 68
#define BS_STRIDE 72
#define AS_SZ (64 * AS_STRIDE)
#define BS_SZ (64 * BS_STRIDE)
#define GATES_SMEM ((6 * AS_SZ + 6 * BS_SZ) * sizeof(float))   // 215040 B
#define RS_STRIDE 66

__global__ void __launch_bounds__(256) gates_gemm_tc() {
    extern __shared__ float smem[];
    float* Abase = smem;
    float* Bbase = smem + 6 * AS_SZ;

    const int tid = threadIdx.x;
    const int gtid = tid & 127;
    const int group = tid >> 7;
    const int m0 = blockIdx.y * 64, n0 = blockIdx.x * 64;
    const int wid4 = (tid >> 5) & 3, lane = tid & 31;
    const int wm = (wid4 >> 1) * 32, wn = (wid4 & 1) * 32;
    const int grp = lane >> 2, tg = lane & 3;

    float acc[2][4][4];
#pragma unroll
    for (int i = 0; i < 2; i++)
#pragma unroll
        for (int j = 0; j < 4; j++)
#pragma unroll
            for (int e = 0; e < 4; e++) acc[i][j][e] = 0.f;

    auto issue = [&](int c, int st) {
        float* a = Abase + (group * 3 + st) * AS_SZ;
        float* b = Bbase + (group * 3 + st) * BS_SZ;
#pragma unroll
        for (int i = 0; i < 8; i++) {
            int s = i * 128 + gtid;
            int row = s >> 4, cs = (s & 15) * 4;
            const float* ga = (c < FCH)
                ? g_feat + (size_t)(m0 + row) * FEATSZ + c * GCH + cs
                : g_h    + (size_t)(m0 + row) * HID + (c - FCH) * GCH + cs;
            cpasync16(a + row * AS_STRIDE + cs, ga);
            const float* gb = (c < FCH)
                ? g_w1t + (size_t)(c * GCH + row) * GATESZ + n0 + cs
                : g_w2t + (size_t)((c - FCH) * GCH + row) * GATESZ + n0 + cs;
            cpasync16(b + row * BS_STRIDE + cs, gb);
        }
    };

    const int c0 = group * HCH;
    issue(c0, 0);
    cp_commit();
    issue(c0 + 1, 1);
    cp_commit();

    for (int ci = 0; ci < HCH; ci++) {
        if (ci + 2 < HCH) {
            issue(c0 + ci + 2, (ci + 2) % 3);
            cp_commit();
            cp_wait<2>();
        } else if (ci + 1 < HCH) {
            cp_wait<1>();
        } else {
            cp_wait<0>();
        }
        grp_bar(group + 1);

        const int st = ci % 3;
        const float* a_s = Abase + (group * 3 + st) * AS_SZ;
        const float* b_s = Bbase + (group * 3 + st) * BS_SZ;
#pragma unroll
        for (int kk = 0; kk < 8; kk++) {
            const int kb = kk * 8;
            unsigned a[2][4], b[4][2];
#pragma unroll
            for (int i = 0; i < 2; i++) {
                int r = wm + i * 16 + grp;
                a[i][0] = __float_as_uint(a_s[r * AS_STRIDE + kb + tg]);
                a[i][1] = __float_as_uint(a_s[(r + 8) * AS_STRIDE + kb + tg]);
                a[i][2] = __float_as_uint(a_s[r * AS_STRIDE + kb + tg + 4]);
                a[i][3] = __float_as_uint(a_s[(r + 8) * AS_STRIDE + kb + tg + 4]);
            }
#pragma unroll
            for (int j = 0; j < 4; j++) {
                int cn = wn + j * 8 + grp;
                b[j][0] = __float_as_uint(b_s[(kb + tg) * BS_STRIDE + cn]);
                b[j][1] = __float_as_uint(b_s[(kb + tg + 4) * BS_STRIDE + cn]);
            }
#pragma unroll
            for (int i = 0; i < 2; i++)
#pragma unroll
                for (int j = 0; j < 4; j++)
                    mma_tf32(acc[i][j], a[i], b[j]);
        }
        grp_bar(group + 1);
    }

    // cross-group reduction
    float* Rs = smem;
    __syncthreads();
    if (group == 1) {
#pragma unroll
        for (int i = 0; i < 2; i++)
#pragma unroll
            for (int j = 0; j < 4; j++) {
                int lr = wm + i * 16 + grp;
                int lc = wn + j * 8 + tg * 2;
                *(float2*)&Rs[lr * RS_STRIDE + lc] = make_float2(acc[i][j][0], acc[i][j][1]);
                *(float2*)&Rs[(lr + 8) * RS_STRIDE + lc] = make_float2(acc[i][j][2], acc[i][j][3]);
            }
    }
    __syncthreads();
    if (group == 0) {
#pragma unroll
        for (int i = 0; i < 2; i++)
#pragma unroll
            for (int j = 0; j < 4; j++) {
                int lr = wm + i * 16 + grp;
                int lc = wn + j * 8 + tg * 2;
                float2 p0 = *(const float2*)&Rs[lr * RS_STRIDE + lc];
                float2 p1 = *(const float2*)&Rs[(lr + 8) * RS_STRIDE + lc];
                int row = m0 + lr;
                int col = n0 + lc;
                *(float2*)&g_gates[(size_t)row * GATESZ + col] =
                    make_float2(acc[i][j][0] + p0.x, acc[i][j][1] + p0.y);
                *(float2*)&g_gates[(size_t)(row + 8) * GATESZ + col] =
                    make_float2(acc[i][j][2] + p1.x, acc[i][j][3] + p1.y);
            }
    }
}

// ---------------- LSTM pointwise (fast transcendentals, RNA rounding on h) ----------------
__global__ void lstm_pw(const float* __restrict__ b_ih, const float* __restrict__ b_hh) {
    int idx = blockIdx.x * blockDim.x + threadIdx.x;
    int b = idx >> 7, j = idx & 127;
    const float* g = g_gates + (size_t)b * GATESZ;
    float gi = g[j]        + b_ih[j]        + b_hh[j];
    float gf = g[128 + j]  + b_ih[128 + j]  + b_hh[128 + j];
    float gg = g[256 + j]  + b_ih[256 + j]  + b_hh[256 + j];
    float go = g[384 + j]  + b_ih[384 + j]  + b_hh[384 + j];
    float cn = sigf(gf) * g_c[idx] + sigf(gi) * tanf_fast(gg);
    g_c[idx] = cn;
    g_h[idx] = __uint_as_float(f2tf32(sigf(go) * tanf_fast(cn)));
}

// ---------------- mask+act head GEMM: 2 n-tiles per block, shared A (R13) ----------------
#define MAS_STRIDE 132
#define MAS_SZ (64 * MAS_STRIDE)
#define MBS_SZ (128 * BS_STRIDE)
#define MASK_SMEM ((MAS_SZ + 2 * MBS_SZ) * sizeof(float))

__global__ void __launch_bounds__(256) maskact_gemm(const float* __restrict__ msk_b,
                                                    const float* __restrict__ act_b,
                                                    float* __restrict__ out_msks,
                                                    float* __restrict__ out_acts, int t) {
    extern __shared__ float smem[];
    float* As = smem;
    const int tid = threadIdx.x;
    const int gtid = tid & 127;
    const int group = tid >> 7;
    float* Bs = smem + MAS_SZ + group * MBS_SZ;

    const int n0 = blockIdx.x * 128 + group * 64;
    const int m0 = blockIdx.y * 64;
    const int wid4 = (tid >> 5) & 3, lane = tid & 31;
    const int wm = (wid4 >> 1) * 32, wn = (wid4 & 1) * 32;
    const int grp = lane >> 2, tg = lane & 3;

#pragma unroll
    for (int i = 0; i < 8; i++) {
        int s = i * 256 + tid;
        int row = s >> 5, cs = (s & 31) * 4;
        cpasync16(As + row * MAS_STRIDE + cs, g_h + (size_t)(m0 + row) * HID + cs);
    }
#pragma unroll
    for (int i = 0; i < 16; i++) {
        int s = i * 128 + gtid;
        int row = s >> 4, cs = (s & 15) * 4;
        cpasync16(Bs + row * BS_STRIDE + cs, g_wmt + (size_t)row * MWID + n0 + cs);
    }
    cp_commit();
    cp_wait<0>();
    __syncthreads();

    float acc[2][4][4];
#pragma unroll
    for (int i = 0; i < 2; i++)
#pragma unroll
        for (int j = 0; j < 4; j++)
#pragma unroll
            for (int e = 0; e < 4; e++) acc[i][j][e] = 0.f;

#pragma unroll
    for (int kk = 0; kk < 16; kk++) {
        const int kb = kk * 8;
        unsigned a[2][4], b[4][2];
#pragma unroll
        for (int i = 0; i < 2; i++) {
            int r = wm + i * 16 + grp;
            a[i][0] = __float_as_uint(As[r * MAS_STRIDE + kb + tg]);
            a[i][1] = __float_as_uint(As[(r + 8) * MAS_STRIDE + kb + tg]);
            a[i][2] = __float_as_uint(As[r * MAS_STRIDE + kb + tg + 4]);
            a[i][3] = __float_as_uint(As[(r + 8) * MAS_STRIDE + kb + tg + 4]);
        }
#pragma unroll
        for (int j = 0; j < 4; j++) {
            int cn = wn + j * 8 + grp;
            b[j][0] = __float_as_uint(Bs[(kb + tg) * BS_STRIDE + cn]);
            b[j][1] = __float_as_uint(Bs[(kb + tg + 4) * BS_STRIDE + cn]);
        }
#pragma unroll
        for (int i = 0; i < 2; i++)
#pragma unroll
            for (int j = 0; j < 4; j++)
                mma_tf32(acc[i][j], a[i], b[j]);
    }

#pragma unroll
    for (int i = 0; i < 2; i++) {
#pragma unroll
        for (int j = 0; j < 4; j++) {
            int row = m0 + wm + i * 16 + grp;
            int col = n0 + wn + j * 8 + tg * 2;
#pragma unroll
            for (int e = 0; e < 4; e++) {
                int m = row + (e >> 1) * 8;
                int n = col + (e & 1);
                float x = acc[i][j][e];
                if (n < 900) {
                    float v = sigf(x + msk_b[n]);
                    g_msk[(size_t)m * 900 + n] = v;
                    out_msks[((size_t)m * TSTEPS + t) * 900 + n] = v;
                } else if (n < 926) {
                    out_acts[((size_t)m * TSTEPS + t) * ACTD + (n - 900)] = x + act_b[n - 900];
                }
            }
        }
    }
}

// ---------------- launch ----------------
extern "C" void kernel_launch(void* const* d_in, const int* in_sizes, int n_in,
                              void* d_out, int out_size) {
    const float* batch = (const float*)d_in[0];
    const float* c1w   = (const float*)d_in[1];
    const float* c1b   = (const float*)d_in[2];
    const float* c2w   = (const float*)d_in[3];
    const float* c2b   = (const float*)d_in[4];
    const float* c3w   = (const float*)d_in[5];
    const float* c3b   = (const float*)d_in[6];
    const float* w_ih  = (const float*)d_in[7];
    const float* w_hh  = (const float*)d_in[8];
    const float* b_ih  = (const float*)d_in[9];
    const float* b_hh  = (const float*)d_in[10];
    const float* msk_w = (const float*)d_in[11];
    const float* msk_b = (const float*)d_in[12];
    const float* act_w = (const float*)d_in[13];
    const float* act_b = (const float*)d_in[14];

    float* out_acts = (float*)d_out;
    float* out_msks = out_acts + (size_t)BATCH * TSTEPS * ACTD;

    const size_t conv_smem = (900 + 6272 + 5408) * sizeof(float2) + 2 * 576 * sizeof(float);
    cudaFuncSetAttribute(conv_kernel, cudaFuncAttributeMaxDynamicSharedMemorySize,
                         (int)conv_smem);
    cudaFuncSetAttribute(gates_gemm_tc, cudaFuncAttributeMaxDynamicSharedMemorySize,
                         (int)GATES_SMEM);
    cudaFuncSetAttribute(maskact_gemm, cudaFuncAttributeMaxDynamicSharedMemorySize,
                         (int)MASK_SMEM);

    init_state<<<(BATCH * 900 + 255) / 256, 256>>>();
    transpose_wih<<<dim3(FEATSZ / 32, GATESZ / 32), dim3(32, 8)>>>(w_ih);
    transpose_whh<<<(HID * GATESZ + 255) / 256, 256>>>(w_hh);
    transpose_wm<<<(HID * MWID + 255) / 256, 256>>>(msk_w, act_w);

    for (int t = 0; t < TSTEPS; t++) {
        conv_kernel<<<BATCH / 2, 256, conv_smem>>>(batch, c1w, c1b, c2w, c2b, c3w, c3b);
        gates_gemm_tc<<<dim3(GATESZ / 64, BATCH / 64), 256, GATES_SMEM>>>();
        lstm_pw<<<BATCH * HID / 256, 256>>>(b_ih, b_hh);
        maskact_gemm<<<dim3(MWID / 128, BATCH / 64), 256, MASK_SMEM>>>(msk_b, act_b,
                                                                       out_msks, out_acts, t);
    }
}